// round 1
// baseline (speedup 1.0000x reference)
#include <cuda_runtime.h>
#include <cfloat>
#include <math.h>

// Problem constants
#define BATCH    4096
#define NROWS    8192          // 2*BATCH
#define DIM      256
#define TEMP_INV 2.0f          // 1 / 0.5

// Tiling for the fused GEMM + online-logsumexp kernel
#define BM 32                  // rows per block
#define BN 64                  // cols per tile
#define LDSTR 260              // shared row stride (floats): 16B-aligned, conflict-spreading
#define SMEM_BYTES ((BM + BN) * LDSTR * 4)

// Scratch (device globals: no runtime allocation allowed)
__device__ float g_z[NROWS * DIM];       // normalized embeddings, 8 MB (fits L2)
__device__ float g_rowloss[NROWS];

// ---------------------------------------------------------------------------
// Kernel 1: row L2-normalization of concat(emb_i, emb_j)
// One block (64 threads) per row; each thread owns one float4 (4*64 = 256).
// ---------------------------------------------------------------------------
__global__ void k_normalize(const float* __restrict__ ei,
                            const float* __restrict__ ej)
{
    int row = blockIdx.x;
    const float* src = (row < BATCH) ? (ei + (size_t)row * DIM)
                                     : (ej + (size_t)(row - BATCH) * DIM);
    int t = threadIdx.x;          // 0..63
    float4 v = ((const float4*)src)[t];
    float ss = v.x * v.x + v.y * v.y + v.z * v.z + v.w * v.w;

    #pragma unroll
    for (int o = 16; o > 0; o >>= 1)
        ss += __shfl_xor_sync(0xFFFFFFFFu, ss, o);

    __shared__ float sred[2];
    if ((t & 31) == 0) sred[t >> 5] = ss;
    __syncthreads();
    float inv = rsqrtf(sred[0] + sred[1]);

    float4 o4 = make_float4(v.x * inv, v.y * inv, v.z * inv, v.w * inv);
    ((float4*)(g_z + (size_t)row * DIM))[t] = o4;
}

// ---------------------------------------------------------------------------
// Kernel 2: fused z @ z^T with online logsumexp + positive-logit extraction.
// Grid: 256 blocks (one 32-row stripe each). Each block sweeps all 8192
// columns in 64-wide tiles. Thread layout: tx = lane (0..31) -> columns
// {cb+tx, cb+tx+32}; ty = warp (0..7) -> rows {rb+ty*4 .. rb+ty*4+3}.
// Each row is owned by exactly one warp -> epilogue is warp-shuffle only.
// ---------------------------------------------------------------------------
__global__ __launch_bounds__(256, 2) void k_main()
{
    extern __shared__ float sm[];
    float* As = sm;                    // [BM][LDSTR]
    float* Bs = sm + BM * LDSTR;       // [BN][LDSTR]

    const int t  = threadIdx.x;
    const int tx = t & 31;
    const int ty = t >> 5;
    const int rb = blockIdx.x * BM;

    // Load A stripe (32 rows x 256) into shared. 2048 float4 / 256 threads = 8.
    #pragma unroll
    for (int it = 0; it < 8; ++it) {
        int idx = t + it * 256;
        int k4  = idx & 63;            // float4 index along k
        int r   = idx >> 6;            // row within stripe
        float4 v = ((const float4*)(g_z + (size_t)(rb + r) * DIM))[k4];
        *(float4*)(As + r * LDSTR + k4 * 4) = v;
    }

    // Per-thread online-softmax state for 4 owned rows
    float m[4], s[4], pv[4];
    #pragma unroll
    for (int j = 0; j < 4; ++j) { m[j] = -FLT_MAX; s[j] = 0.f; pv[j] = -FLT_MAX; }

    const int ir0 = rb + ty * 4;

    for (int ct = 0; ct < NROWS / BN; ++ct) {
        const int cb = ct * BN;

        __syncthreads();   // previous tile's reads of Bs done
        // Load B tile (64 rows x 256). 4096 float4 / 256 threads = 16.
        #pragma unroll
        for (int it = 0; it < 16; ++it) {
            int idx = t + it * 256;
            int k4  = idx & 63;
            int c   = idx >> 6;
            float4 v = ((const float4*)(g_z + (size_t)(cb + c) * DIM))[k4];
            *(float4*)(Bs + c * LDSTR + k4 * 4) = v;
        }
        __syncthreads();

        float acc[4][2];
        #pragma unroll
        for (int j = 0; j < 4; ++j) { acc[j][0] = 0.f; acc[j][1] = 0.f; }

        #pragma unroll 4
        for (int k4 = 0; k4 < 64; ++k4) {
            float4 b0 = *(const float4*)(Bs + tx * LDSTR + k4 * 4);
            float4 b1 = *(const float4*)(Bs + (tx + 32) * LDSTR + k4 * 4);
            #pragma unroll
            for (int j = 0; j < 4; ++j) {
                float4 a = *(const float4*)(As + (ty * 4 + j) * LDSTR + k4 * 4);
                acc[j][0] = fmaf(a.x, b0.x, acc[j][0]);
                acc[j][0] = fmaf(a.y, b0.y, acc[j][0]);
                acc[j][0] = fmaf(a.z, b0.z, acc[j][0]);
                acc[j][0] = fmaf(a.w, b0.w, acc[j][0]);
                acc[j][1] = fmaf(a.x, b1.x, acc[j][1]);
                acc[j][1] = fmaf(a.y, b1.y, acc[j][1]);
                acc[j][1] = fmaf(a.z, b1.z, acc[j][1]);
                acc[j][1] = fmaf(a.w, b1.w, acc[j][1]);
            }
        }

        // Online-softmax update; mask diagonal; capture positive logit.
        #pragma unroll
        for (int j = 0; j < 4; ++j) {
            const int ir = ir0 + j;
            const int p  = (ir < BATCH) ? (ir + BATCH) : (ir - BATCH);
            #pragma unroll
            for (int i = 0; i < 2; ++i) {
                const int jc = cb + tx + i * 32;
                float v = TEMP_INV * acc[j][i];
                if (jc != ir) {
                    if (jc == p) pv[j] = v;
                    float mn = fmaxf(m[j], v);
                    s[j] = s[j] * __expf(m[j] - mn) + __expf(v - mn);
                    m[j] = mn;
                }
            }
        }
    }

    // Warp reduction: each warp owns 4 complete rows.
    #pragma unroll
    for (int j = 0; j < 4; ++j) {
        float mx = m[j];
        #pragma unroll
        for (int o = 16; o > 0; o >>= 1)
            mx = fmaxf(mx, __shfl_xor_sync(0xFFFFFFFFu, mx, o));
        float sl = s[j] * __expf(m[j] - mx);
        #pragma unroll
        for (int o = 16; o > 0; o >>= 1)
            sl += __shfl_xor_sync(0xFFFFFFFFu, sl, o);
        float pp = pv[j];
        #pragma unroll
        for (int o = 16; o > 0; o >>= 1)
            pp = fmaxf(pp, __shfl_xor_sync(0xFFFFFFFFu, pp, o));
        if (tx == 0)
            g_rowloss[ir0 + j] = (mx + logf(sl)) - pp;
    }
}

// ---------------------------------------------------------------------------
// Kernel 3: deterministic mean of the 8192 per-row losses.
// ---------------------------------------------------------------------------
__global__ void k_reduce(float* __restrict__ out)
{
    int t = threadIdx.x;   // 256
    float s = 0.f;
    for (int i = t; i < NROWS; i += 256) s += g_rowloss[i];

    #pragma unroll
    for (int o = 16; o > 0; o >>= 1)
        s += __shfl_xor_sync(0xFFFFFFFFu, s, o);

    __shared__ float red[8];
    if ((t & 31) == 0) red[t >> 5] = s;
    __syncthreads();
    if (t < 8) {
        float v = red[t];
        #pragma unroll
        for (int o = 4; o > 0; o >>= 1)
            v += __shfl_xor_sync(0xFFu, v, o);
        if (t == 0) out[0] = v / (float)NROWS;
    }
}

// ---------------------------------------------------------------------------
extern "C" void kernel_launch(void* const* d_in, const int* in_sizes, int n_in,
                              void* d_out, int out_size)
{
    const float* ei = (const float*)d_in[0];
    const float* ej = (const float*)d_in[1];
    float* out = (float*)d_out;

    (void)in_sizes; (void)n_in; (void)out_size;

    cudaFuncSetAttribute(k_main, cudaFuncAttributeMaxDynamicSharedMemorySize,
                         SMEM_BYTES);

    k_normalize<<<NROWS, 64>>>(ei, ej);
    k_main<<<NROWS / BM, 256, SMEM_BYTES>>>();
    k_reduce<<<1, 256>>>(out);
}

// round 3
// speedup vs baseline: 9.4685x; 9.4685x over previous
#include <cuda_runtime.h>
#include <cuda_bf16.h>
#include <cstdint>

// ---------------------------------------------------------------- constants
#define BATCH 4096
#define NROWS 8192
#define DIM   256

#define LN2f   0.69314718055994531f
#define CBIAS  2.8853900817779268f     // 2*log2(e): fixed softmax max (sim/T <= 2)
#define SCALE  1.6986442f              // sqrt(2*log2(e)) folded into z (both sides)

#define BM 128                         // rows per CTA
#define BN 128                         // cols per B tile
#define CSPLIT 4                       // column splits across CTAs
#define NT 16                          // (8192/CSPLIT)/BN tiles per CTA

#define LDH 264                        // smem row pitch in halves (33*16B -> stride 1 mod 8)
#define TILE_BYTES (128 * LDH * 2)     // 67584
#define SMEM_A  0
#define SMEM_B0 TILE_BYTES
#define SMEM_B1 (2 * TILE_BYTES)
#define SMEM_TOTAL (3 * TILE_BYTES)    // 202752 < 227KB

// ------------------------------------------------------------ device scratch
__device__ __align__(16) __nv_bfloat16 g_zb[NROWS * DIM];  // normalized*SCALE, bf16
__device__ float g_ps[2 * CSPLIT][NROWS];                  // partial sum of 2^(u-C)
__device__ float g_pp[2 * CSPLIT][NROWS];                  // positive logit (log2 dom)

// ------------------------------------------------------------- asm helpers
__device__ __forceinline__ uint32_t smem_u32(const void* p) {
    uint32_t a;
    asm("{ .reg .u64 t; cvta.to.shared.u64 t, %1; cvt.u32.u64 %0, t; }" : "=r"(a) : "l"(p));
    return a;
}
__device__ __forceinline__ float ex2f(float x) {
    float y; asm("ex2.approx.ftz.f32 %0, %1;" : "=f"(y) : "f"(x)); return y;
}
__device__ __forceinline__ float lg2f(float x) {
    float y; asm("lg2.approx.f32 %0, %1;" : "=f"(y) : "f"(x)); return y;
}
__device__ __forceinline__ void cp16(uint32_t s, const void* g) {
    asm volatile("cp.async.cg.shared.global [%0], [%1], 16;" :: "r"(s), "l"(g));
}
__device__ __forceinline__ void cp_commit() {
    asm volatile("cp.async.commit_group;");
}
__device__ __forceinline__ void cp_wait0() {
    asm volatile("cp.async.wait_group 0;" ::: "memory");
}
__device__ __forceinline__ void ldmx4(uint32_t* r, uint32_t addr) {
    asm volatile("ldmatrix.sync.aligned.m8n8.x4.shared.b16 {%0,%1,%2,%3}, [%4];"
                 : "=r"(r[0]), "=r"(r[1]), "=r"(r[2]), "=r"(r[3]) : "r"(addr));
}
__device__ __forceinline__ void mma16816(float* c, const uint32_t* a,
                                         uint32_t b0, uint32_t b1) {
    asm volatile("mma.sync.aligned.m16n8k16.row.col.f32.bf16.bf16.f32 "
                 "{%0,%1,%2,%3}, {%4,%5,%6,%7}, {%8,%9}, {%0,%1,%2,%3};"
                 : "+f"(c[0]), "+f"(c[1]), "+f"(c[2]), "+f"(c[3])
                 : "r"(a[0]), "r"(a[1]), "r"(a[2]), "r"(a[3]), "r"(b0), "r"(b1));
}

// 128-row x 256-col bf16 tile: global row-major -> smem padded rows (async)
__device__ __forceinline__ void load_tile_async(const __nv_bfloat16* __restrict__ g,
                                                uint32_t sdst)
{
    int t = threadIdx.x;
    const char* gb = (const char*)g;
    #pragma unroll
    for (int it = 0; it < 16; ++it) {
        int idx = t + it * 256;           // 0..4095 16B chunks
        int row = idx >> 5;               // 32 chunks per row (512B)
        int ck  = idx & 31;
        cp16(sdst + row * (LDH * 2) + ck * 16, gb + row * 512 + ck * 16);
    }
}

// ---------------------------------------------------------------------------
// Kernel 1: row L2-normalization -> scaled bf16
// ---------------------------------------------------------------------------
__global__ void k_normalize(const float* __restrict__ ei,
                            const float* __restrict__ ej)
{
    int row = blockIdx.x;
    const float* src = (row < BATCH) ? (ei + (size_t)row * DIM)
                                     : (ej + (size_t)(row - BATCH) * DIM);
    int t = threadIdx.x;          // 0..63
    float4 v = ((const float4*)src)[t];
    float ss = v.x * v.x + v.y * v.y + v.z * v.z + v.w * v.w;
    #pragma unroll
    for (int o = 16; o > 0; o >>= 1) ss += __shfl_xor_sync(0xFFFFFFFFu, ss, o);
    __shared__ float sred[2];
    if ((t & 31) == 0) sred[t >> 5] = ss;
    __syncthreads();
    float inv = rsqrtf(sred[0] + sred[1]) * SCALE;

    __nv_bfloat162 h0 = __floats2bfloat162_rn(v.x * inv, v.y * inv);
    __nv_bfloat162 h1 = __floats2bfloat162_rn(v.z * inv, v.w * inv);
    uint2 o2;
    o2.x = *reinterpret_cast<uint32_t*>(&h0);
    o2.y = *reinterpret_cast<uint32_t*>(&h1);
    ((uint2*)(g_zb + (size_t)row * DIM))[t] = o2;
}

// ---------------------------------------------------------------------------
// Kernel 2: fused bf16 HMMA GEMM (z z^T scaled) + exp2 sum + positive capture.
// grid = (64 row stripes, CSPLIT col splits), 256 threads = 8 warps (4x2).
// Warp tile 32 rows x 64 cols; accumulators in registers.
// ---------------------------------------------------------------------------
__global__ __launch_bounds__(256, 1) void k_main()
{
    extern __shared__ char sm[];
    const uint32_t sb = smem_u32(sm);
    const int t    = threadIdx.x;
    const int lane = t & 31;
    const int wid  = t >> 5;
    const int wr   = wid >> 1;           // warp row 0..3
    const int wc   = wid & 1;            // warp col 0..1
    const int rb   = blockIdx.x * BM;
    const int cb0  = blockIdx.y * (NROWS / CSPLIT);

    // prologue: A stripe + first B tile
    load_tile_async(g_zb + (size_t)rb * DIM, sb + SMEM_A);
    load_tile_async(g_zb + (size_t)cb0 * DIM, sb + SMEM_B0);
    cp_commit();
    cp_wait0();
    __syncthreads();

    // per-thread identity
    const int q  = lane >> 2;
    const int c2 = (lane & 3) * 2;
    int ir[4], pc[4];
    #pragma unroll
    for (int mb = 0; mb < 2; ++mb)
        #pragma unroll
        for (int h = 0; h < 2; ++h) {
            int ri = mb * 2 + h;
            int r  = rb + wr * 32 + mb * 16 + h * 8 + q;
            ir[ri] = r;
            pc[ri] = (r < BATCH) ? r + BATCH : r - BATCH;
        }
    float s[4]  = {0.f, 0.f, 0.f, 0.f};
    float pu[4] = {0.f, 0.f, 0.f, 0.f};

    // ldmatrix addresses
    uint32_t aaddr[2];
    #pragma unroll
    for (int mb = 0; mb < 2; ++mb) {
        int arow = wr * 32 + mb * 16 + (lane & 15);
        aaddr[mb] = sb + SMEM_A + (uint32_t)(arow * LDH + (lane >> 4) * 8) * 2;
    }
    uint32_t boff[4];
    {
        int nsub = ((lane >> 4) << 3) + (lane & 7);
        int koff = ((lane >> 3) & 1) * 8;
        #pragma unroll
        for (int nb16 = 0; nb16 < 4; ++nb16) {
            int n = wc * 64 + nb16 * 16 + nsub;
            boff[nb16] = (uint32_t)(n * LDH + koff) * 2;
        }
    }

    #pragma unroll 1
    for (int ti = 0; ti < NT; ++ti) {
        const uint32_t bbase = sb + ((ti & 1) ? SMEM_B1 : SMEM_B0);

        if (ti + 1 < NT) {
            load_tile_async(g_zb + (size_t)(cb0 + (ti + 1) * BN) * DIM,
                            sb + ((ti & 1) ? SMEM_B0 : SMEM_B1));
            cp_commit();
        }

        float c[2][8][4];
        #pragma unroll
        for (int mb = 0; mb < 2; ++mb)
            #pragma unroll
            for (int nb = 0; nb < 8; ++nb)
                #pragma unroll
                for (int e = 0; e < 4; ++e) c[mb][nb][e] = 0.f;

        #pragma unroll
        for (int ks = 0; ks < 16; ++ks) {
            uint32_t af[2][4], bf[4][4];
            #pragma unroll
            for (int mb = 0; mb < 2; ++mb)
                ldmx4(af[mb], aaddr[mb] + ks * 32);
            #pragma unroll
            for (int nb16 = 0; nb16 < 4; ++nb16)
                ldmx4(bf[nb16], bbase + boff[nb16] + ks * 32);
            #pragma unroll
            for (int mb = 0; mb < 2; ++mb)
                #pragma unroll
                for (int nb = 0; nb < 8; ++nb) {
                    const uint32_t* bp = bf[nb >> 1];
                    uint32_t b0 = (nb & 1) ? bp[2] : bp[0];
                    uint32_t b1 = (nb & 1) ? bp[3] : bp[1];
                    mma16816(c[mb][nb], af[mb], b0, b1);
                }
        }

        // fused epilogue: e = 2^(u - C), masked diag, positive capture
        const int cbase = cb0 + ti * BN + wc * 64;
        #pragma unroll
        for (int mb = 0; mb < 2; ++mb)
            #pragma unroll
            for (int nb = 0; nb < 8; ++nb)
                #pragma unroll
                for (int e = 0; e < 4; ++e) {
                    float u  = c[mb][nb][e];
                    int   jc = cbase + nb * 8 + c2 + (e & 1);
                    int   ri = mb * 2 + (e >> 1);
                    float ex = ex2f(u - CBIAS);
                    if (jc != ir[ri]) s[ri]  += ex;
                    if (jc == pc[ri]) pu[ri] += u;
                }

        if (ti + 1 < NT) {
            cp_wait0();
            __syncthreads();
        }
    }

    // reduce over the 4 lanes sharing the same rows (lane bits 0,1)
    const int part = blockIdx.y * 2 + wc;
    #pragma unroll
    for (int ri = 0; ri < 4; ++ri) {
        float sv = s[ri], pv = pu[ri];
        sv += __shfl_xor_sync(0xFFFFFFFFu, sv, 1);
        sv += __shfl_xor_sync(0xFFFFFFFFu, sv, 2);
        pv += __shfl_xor_sync(0xFFFFFFFFu, pv, 1);
        pv += __shfl_xor_sync(0xFFFFFFFFu, pv, 2);
        if ((lane & 3) == 0) {
            g_ps[part][ir[ri]] = sv;
            g_pp[part][ir[ri]] = pv;
        }
    }
}

// ---------------------------------------------------------------------------
// Kernel 3: combine partials, deterministic mean loss
// loss_row = ln2 * (CBIAS + log2(S) - pu)
// ---------------------------------------------------------------------------
__global__ void k_reduce(float* __restrict__ out)
{
    int t = threadIdx.x;   // 256
    float acc = 0.f;
    for (int r = t; r < NROWS; r += 256) {
        float S = 0.f, P = 0.f;
        #pragma unroll
        for (int p = 0; p < 2 * CSPLIT; ++p) {
            S += g_ps[p][r];
            P += g_pp[p][r];
        }
        acc += LN2f * (CBIAS + lg2f(S) - P);
    }
    #pragma unroll
    for (int o = 16; o > 0; o >>= 1) acc += __shfl_xor_sync(0xFFFFFFFFu, acc, o);
    __shared__ float red[8];
    if ((t & 31) == 0) red[t >> 5] = acc;
    __syncthreads();
    if (t < 8) {
        float v = red[t];
        #pragma unroll
        for (int o = 4; o > 0; o >>= 1) v += __shfl_xor_sync(0xFFu, v, o);
        if (t == 0) out[0] = v / (float)NROWS;
    }
}

// ---------------------------------------------------------------------------
extern "C" void kernel_launch(void* const* d_in, const int* in_sizes, int n_in,
                              void* d_out, int out_size)
{
    const float* ei = (const float*)d_in[0];
    const float* ej = (const float*)d_in[1];
    float* out = (float*)d_out;
    (void)in_sizes; (void)n_in; (void)out_size;

    cudaFuncSetAttribute(k_main, cudaFuncAttributeMaxDynamicSharedMemorySize,
                         SMEM_TOTAL);

    k_normalize<<<NROWS, 64>>>(ei, ej);
    k_main<<<dim3(NROWS / BM, CSPLIT), 256, SMEM_TOTAL>>>();
    k_reduce<<<1, 256>>>(out);
}

// round 4
// speedup vs baseline: 9.8268x; 1.0378x over previous
#include <cuda_runtime.h>
#include <cuda_bf16.h>
#include <cstdint>

// ---------------------------------------------------------------- constants
#define BATCH 4096
#define NROWS 8192
#define DIM   256

#define LN2f   0.69314718055994531f
#define SCALE  1.6986442f              // sqrt(2*log2(e)): folds 1/T and log2(e) into z

#define BM 128                         // rows per CTA
#define BN 32                          // cols per B tile
#define CSPLIT 4                       // column splits across CTAs
#define NT 64                          // (8192/CSPLIT)/BN tiles per CTA

#define LDH 264                        // smem pitch in halves (16B-aligned, odd mod 8)
#define A_BYTES (128 * LDH * 2)        // 67584
#define B_BYTES (BN * LDH * 2)         // 16896
#define SMEM_A  0
#define SMEM_B0 A_BYTES
#define SMEM_B1 (A_BYTES + B_BYTES)
#define SMEM_TOTAL (A_BYTES + 2 * B_BYTES)   // 101376 -> 2 CTAs/SM

// ------------------------------------------------------------ device scratch
__device__ __align__(16) __nv_bfloat16 g_zb[NROWS * DIM];  // normalized*SCALE bf16
__device__ float g_ps[2 * CSPLIT][NROWS];                  // partial sums of 2^u
__device__ float g_diag[NROWS];                            // u at diagonal
__device__ float g_pos[NROWS];                             // u at positive pair
__device__ float g_blk[32];                                // reduce stage-1 out

// ------------------------------------------------------------- asm helpers
__device__ __forceinline__ uint32_t smem_u32(const void* p) {
    uint32_t a;
    asm("{ .reg .u64 t; cvta.to.shared.u64 t, %1; cvt.u32.u64 %0, t; }" : "=r"(a) : "l"(p));
    return a;
}
__device__ __forceinline__ float ex2f(float x) {
    float y; asm("ex2.approx.ftz.f32 %0, %1;" : "=f"(y) : "f"(x)); return y;
}
__device__ __forceinline__ float lg2f(float x) {
    float y; asm("lg2.approx.f32 %0, %1;" : "=f"(y) : "f"(x)); return y;
}
__device__ __forceinline__ void cp16(uint32_t s, const void* g) {
    asm volatile("cp.async.cg.shared.global [%0], [%1], 16;" :: "r"(s), "l"(g));
}
__device__ __forceinline__ void cp_commit() { asm volatile("cp.async.commit_group;"); }
__device__ __forceinline__ void cp_wait0()  { asm volatile("cp.async.wait_group 0;" ::: "memory"); }
__device__ __forceinline__ void ldmx4(uint32_t* r, uint32_t addr) {
    asm volatile("ldmatrix.sync.aligned.m8n8.x4.shared.b16 {%0,%1,%2,%3}, [%4];"
                 : "=r"(r[0]), "=r"(r[1]), "=r"(r[2]), "=r"(r[3]) : "r"(addr));
}
__device__ __forceinline__ void mma16816(float* c, const uint32_t* a,
                                         uint32_t b0, uint32_t b1) {
    asm volatile("mma.sync.aligned.m16n8k16.row.col.f32.bf16.bf16.f32 "
                 "{%0,%1,%2,%3}, {%4,%5,%6,%7}, {%8,%9}, {%0,%1,%2,%3};"
                 : "+f"(c[0]), "+f"(c[1]), "+f"(c[2]), "+f"(c[3])
                 : "r"(a[0]), "r"(a[1]), "r"(a[2]), "r"(a[3]), "r"(b0), "r"(b1));
}

// ROWS x 256-col bf16 tile: global row-major -> smem padded rows (async)
template <int R>
__device__ __forceinline__ void load_tile_async(const __nv_bfloat16* __restrict__ g,
                                                uint32_t sdst)
{
    int t = threadIdx.x;
    const char* gb = (const char*)g;
    #pragma unroll
    for (int it = 0; it < R / 8; ++it) {
        int idx = t + it * 256;           // 16B chunks
        int row = idx >> 5;
        int ck  = idx & 31;
        cp16(sdst + row * (LDH * 2) + ck * 16, gb + row * 512 + ck * 16);
    }
}

// ---------------------------------------------------------------------------
// Kernel 1: row L2-normalization -> scaled bf16. One warp per row.
// ---------------------------------------------------------------------------
__global__ __launch_bounds__(256) void k_normalize(const float* __restrict__ ei,
                                                   const float* __restrict__ ej)
{
    int wid  = threadIdx.x >> 5;
    int lane = threadIdx.x & 31;
    int row  = blockIdx.x * 8 + wid;
    const float* src = (row < BATCH) ? (ei + (size_t)row * DIM)
                                     : (ej + (size_t)(row - BATCH) * DIM);
    float4 v0 = ((const float4*)src)[lane];
    float4 v1 = ((const float4*)src)[lane + 32];
    float ss = v0.x*v0.x + v0.y*v0.y + v0.z*v0.z + v0.w*v0.w
             + v1.x*v1.x + v1.y*v1.y + v1.z*v1.z + v1.w*v1.w;
    #pragma unroll
    for (int o = 16; o > 0; o >>= 1) ss += __shfl_xor_sync(0xFFFFFFFFu, ss, o);
    float inv = rsqrtf(ss) * SCALE;

    __nv_bfloat162 a0 = __floats2bfloat162_rn(v0.x*inv, v0.y*inv);
    __nv_bfloat162 a1 = __floats2bfloat162_rn(v0.z*inv, v0.w*inv);
    __nv_bfloat162 b0 = __floats2bfloat162_rn(v1.x*inv, v1.y*inv);
    __nv_bfloat162 b1 = __floats2bfloat162_rn(v1.z*inv, v1.w*inv);
    uint2* dst = (uint2*)(g_zb + (size_t)row * DIM);
    uint2 oa, ob;
    oa.x = *(uint32_t*)&a0; oa.y = *(uint32_t*)&a1;
    ob.x = *(uint32_t*)&b0; ob.y = *(uint32_t*)&b1;
    dst[lane]      = oa;
    dst[lane + 32] = ob;
}

// ---------------------------------------------------------------------------
// Kernel 2: per-row diagonal and positive-pair logits (u units = log2 domain)
// One warp per row.
// ---------------------------------------------------------------------------
__global__ __launch_bounds__(256) void k_pairs()
{
    int wid  = threadIdx.x >> 5;
    int lane = threadIdx.x & 31;
    int row  = blockIdx.x * 8 + wid;
    int par  = (row < BATCH) ? row + BATCH : row - BATCH;

    const uint4 ra = ((const uint4*)(g_zb + (size_t)row * DIM))[lane];
    const uint4 rb = ((const uint4*)(g_zb + (size_t)par * DIM))[lane];
    const __nv_bfloat162* pa = (const __nv_bfloat162*)&ra;
    const __nv_bfloat162* pb = (const __nv_bfloat162*)&rb;

    float d = 0.f, p = 0.f;
    #pragma unroll
    for (int i = 0; i < 4; ++i) {
        float2 a = __bfloat1622float2(pa[i]);
        float2 b = __bfloat1622float2(pb[i]);
        d += a.x * a.x + a.y * a.y;
        p += a.x * b.x + a.y * b.y;
    }
    #pragma unroll
    for (int o = 16; o > 0; o >>= 1) {
        d += __shfl_xor_sync(0xFFFFFFFFu, d, o);
        p += __shfl_xor_sync(0xFFFFFFFFu, p, o);
    }
    if (lane == 0) { g_diag[row] = d; g_pos[row] = p; }
}

// ---------------------------------------------------------------------------
// Kernel 3: bf16 HMMA z z^T (scaled) + unconditional exp2-sum.
// grid = (64 stripes, CSPLIT), 256 threads = 8 warps (4 row x 2 col),
// warp tile 32x16, 2 CTAs/SM.
// ---------------------------------------------------------------------------
__global__ __launch_bounds__(256, 2) void k_main()
{
    extern __shared__ char sm[];
    const uint32_t sb = smem_u32(sm);
    const int t    = threadIdx.x;
    const int lane = t & 31;
    const int wid  = t >> 5;
    const int wr   = wid >> 1;           // 0..3
    const int wc   = wid & 1;            // 0..1
    const int rb   = blockIdx.x * BM;
    const int cb0  = blockIdx.y * (NROWS / CSPLIT);

    load_tile_async<128>(g_zb + (size_t)rb * DIM, sb + SMEM_A);
    load_tile_async<BN>(g_zb + (size_t)cb0 * DIM, sb + SMEM_B0);
    cp_commit();
    cp_wait0();
    __syncthreads();

    // ldmatrix addresses
    uint32_t aaddr[2];
    #pragma unroll
    for (int mb = 0; mb < 2; ++mb) {
        int arow = wr * 32 + mb * 16 + (lane & 15);
        aaddr[mb] = sb + SMEM_A + (uint32_t)(arow * LDH + (lane >> 4) * 8) * 2;
    }
    uint32_t boff;
    {
        int nsub = ((lane >> 4) << 3) + (lane & 7);      // 0..15
        int koff = ((lane >> 3) & 1) * 8;
        boff = (uint32_t)((wc * 16 + nsub) * LDH + koff) * 2;
    }

    float s[4] = {0.f, 0.f, 0.f, 0.f};

    #pragma unroll 1
    for (int ti = 0; ti < NT; ++ti) {
        const uint32_t bbase = sb + ((ti & 1) ? SMEM_B1 : SMEM_B0);

        if (ti + 1 < NT) {
            load_tile_async<BN>(g_zb + (size_t)(cb0 + (ti + 1) * BN) * DIM,
                                sb + ((ti & 1) ? SMEM_B0 : SMEM_B1));
            cp_commit();
        }

        float c[2][2][4];
        #pragma unroll
        for (int mb = 0; mb < 2; ++mb)
            #pragma unroll
            for (int nb = 0; nb < 2; ++nb)
                #pragma unroll
                for (int e = 0; e < 4; ++e) c[mb][nb][e] = 0.f;

        #pragma unroll
        for (int ks = 0; ks < 16; ++ks) {
            uint32_t af[2][4], bf[4];
            ldmx4(af[0], aaddr[0] + ks * 32);
            ldmx4(af[1], aaddr[1] + ks * 32);
            ldmx4(bf, bbase + boff + ks * 32);
            #pragma unroll
            for (int mb = 0; mb < 2; ++mb) {
                mma16816(c[mb][0], af[mb], bf[0], bf[1]);
                mma16816(c[mb][1], af[mb], bf[2], bf[3]);
            }
        }

        // fused epilogue: s += 2^u, no masks (diag/pos handled analytically)
        #pragma unroll
        for (int mb = 0; mb < 2; ++mb)
            #pragma unroll
            for (int nb = 0; nb < 2; ++nb)
                #pragma unroll
                for (int e = 0; e < 4; ++e)
                    s[mb * 2 + (e >> 1)] += ex2f(c[mb][nb][e]);

        if (ti + 1 < NT) {
            cp_wait0();
            __syncthreads();
        }
    }

    // reduce over 4 lanes sharing each row (lane bits 0,1), write partials
    const int part = blockIdx.y * 2 + wc;
    const int q = lane >> 2;
    #pragma unroll
    for (int ri = 0; ri < 4; ++ri) {
        float sv = s[ri];
        sv += __shfl_xor_sync(0xFFFFFFFFu, sv, 1);
        sv += __shfl_xor_sync(0xFFFFFFFFu, sv, 2);
        if ((lane & 3) == 0) {
            int r = rb + wr * 32 + (ri >> 1) * 16 + (ri & 1) * 8 + q;
            g_ps[part][r] = sv;
        }
    }
}

// ---------------------------------------------------------------------------
// Kernel 4a: per-row loss, block partial sums (32 blocks x 256)
// loss_row = ln2 * (log2(S - 2^diag) - pos)
// ---------------------------------------------------------------------------
__global__ __launch_bounds__(256) void k_red1()
{
    int t = threadIdx.x;
    int r0 = blockIdx.x * 256;
    int r = r0 + t;
    float S = 0.f;
    #pragma unroll
    for (int p = 0; p < 2 * CSPLIT; ++p) S += g_ps[p][r];
    S -= ex2f(g_diag[r]);
    float acc = lg2f(S) - g_pos[r];

    #pragma unroll
    for (int o = 16; o > 0; o >>= 1) acc += __shfl_xor_sync(0xFFFFFFFFu, acc, o);
    __shared__ float red[8];
    if ((t & 31) == 0) red[t >> 5] = acc;
    __syncthreads();
    if (t < 8) {
        float v = red[t];
        #pragma unroll
        for (int o = 4; o > 0; o >>= 1) v += __shfl_xor_sync(0xFFu, v, o);
        if (t == 0) g_blk[blockIdx.x] = v;
    }
}

__global__ void k_red2(float* __restrict__ out)
{
    int t = threadIdx.x;  // 32
    float v = g_blk[t];
    #pragma unroll
    for (int o = 16; o > 0; o >>= 1) v += __shfl_xor_sync(0xFFFFFFFFu, v, o);
    if (t == 0) out[0] = v * (LN2f / (float)NROWS);
}

// ---------------------------------------------------------------------------
extern "C" void kernel_launch(void* const* d_in, const int* in_sizes, int n_in,
                              void* d_out, int out_size)
{
    const float* ei = (const float*)d_in[0];
    const float* ej = (const float*)d_in[1];
    float* out = (float*)d_out;
    (void)in_sizes; (void)n_in; (void)out_size;

    cudaFuncSetAttribute(k_main, cudaFuncAttributeMaxDynamicSharedMemorySize,
                         SMEM_TOTAL);

    k_normalize<<<NROWS / 8, 256>>>(ei, ej);
    k_pairs<<<NROWS / 8, 256>>>();
    k_main<<<dim3(NROWS / BM, CSPLIT), 256, SMEM_TOTAL>>>();
    k_red1<<<32, 256>>>();
    k_red2<<<1, 32>>>(out);
}